// round 1
// baseline (speedup 1.0000x reference)
#include <cuda_runtime.h>

#define N_STRUCT 65536
#define B_BATCH  64
#define L_TEXT   256
#define DIM      256
#define HEADS    4
#define HD       64
#define TM       32
#define MAXT     (B_BATCH + N_STRUCT / TM)   // 2112 worst-case tiles

// ---------------- scratch (static device globals; no runtime allocs) ----------------
__device__ float g_Q[N_STRUCT * DIM];          // 64 MB
__device__ float g_K[B_BATCH * L_TEXT * DIM];  // 16 MB
__device__ float g_V[B_BATCH * L_TEXT * DIM];  // 16 MB
__device__ float g_accum[B_BATCH * DIM];
__device__ int   g_offsets[B_BATCH + 1];
__device__ int   g_tileB[MAXT];
__device__ int   g_tileStart[MAXT];
__device__ int   g_tileRows[MAXT];
__device__ int   g_ntiles;

// ---------------- shared-memory layout of the fused tile kernel (floats) ----------------
// sQ   [32][260]    Q tile (one row per struct token)
// sS   [32][260]    scores -> probs -> fused (reused)
// sCtx [32][260]    attention context
// sKV  union: K as [256][65], V as [256][68], Wo chunk as [64][257]
// sCol [256]        per-tile masked column sum
#define SQ_OFF   0
#define SS_OFF   8320
#define SC_OFF   16640
#define KV_OFF   24960
#define COL_OFF  42368
#define SMEM_FLOATS 42624
#define SMEM_BYTES  (SMEM_FLOATS * 4)

// =====================================================================================
// Setup: dtype-detect struct_batch, batch offsets via binary search, tile schedule,
// zero accumulators. Deterministic every launch.
// =====================================================================================
__global__ void setup_kernel(const int* __restrict__ sb)
{
    __shared__ int sIs64;
    __shared__ int sOff[B_BATCH + 1];
    __shared__ int sScan[B_BATCH + 1];
    int tid = threadIdx.x;

    if (tid == 0) {
        // int64 little-endian: word (N-1) is a high word == 0.
        // int32: word (N-1) is the last (max) batch id, ~surely 63 != 0.
        sIs64 = (sb[N_STRUCT - 1] == 0) ? 1 : 0;
    }
    for (int i = tid; i < B_BATCH * DIM; i += blockDim.x) g_accum[i] = 0.f;
    __syncthreads();
    int is64 = sIs64;

    if (tid <= B_BATCH) {
        // first index with sb[i] >= tid  (sorted array)
        int lo = 0, hi = N_STRUCT;
        while (lo < hi) {
            int mid = (lo + hi) >> 1;
            int v = is64 ? sb[2 * mid] : sb[mid];
            if (v < tid) lo = mid + 1; else hi = mid;
        }
        sOff[tid] = lo;
        g_offsets[tid] = lo;
    }
    __syncthreads();
    if (tid < B_BATCH) {
        int cnt = sOff[tid + 1] - sOff[tid];
        sScan[tid] = (cnt + TM - 1) / TM;
    }
    __syncthreads();
    if (tid == 0) {
        int run = 0;
        for (int i = 0; i < B_BATCH; i++) { int t = sScan[i]; sScan[i] = run; run += t; }
        sScan[B_BATCH] = run;
        g_ntiles = run;
    }
    __syncthreads();
    if (tid < B_BATCH) {
        int base = sScan[tid];
        int off  = sOff[tid];
        int cnt  = sOff[tid + 1] - off;
        for (int t = 0; t * TM < cnt; t++) {
            g_tileB[base + t]     = tid;
            g_tileStart[base + t] = off + t * TM;
            g_tileRows[base + t]  = min(TM, cnt - t * TM);
        }
    }
}

// =====================================================================================
// C[M x 256] = A[M x 256] @ W^T + bias.   W row-major [256(+off) x 256].
// Tile 128x64, BK=16, 256 threads, 8x4 per thread. M must be a multiple of 128.
// =====================================================================================
__global__ __launch_bounds__(256) void gemm256(
    const float* __restrict__ A, const float* __restrict__ W,
    const float* __restrict__ bias, float* __restrict__ C)
{
    __shared__ float sA[128][17];
    __shared__ float sW[64][17];
    int tid = threadIdx.x;
    int m0 = blockIdx.x << 7;
    int n0 = blockIdx.y << 6;
    int tr = tid >> 4;   // 0..15 : row group (8 rows each)
    int tc = tid & 15;   // 0..15 : col group (4 cols each)

    float acc[8][4];
#pragma unroll
    for (int i = 0; i < 8; i++)
#pragma unroll
        for (int j = 0; j < 4; j++) acc[i][j] = 0.f;

    for (int k0 = 0; k0 < 256; k0 += 16) {
#pragma unroll
        for (int q = 0; q < 2; q++) {
            int idx = tid + (q << 8);
            int row = idx >> 2;
            int k4  = (idx & 3) << 2;
            float4 v = *(const float4*)&A[(size_t)(m0 + row) * 256 + k0 + k4];
            sA[row][k4 + 0] = v.x; sA[row][k4 + 1] = v.y;
            sA[row][k4 + 2] = v.z; sA[row][k4 + 3] = v.w;
        }
        {
            int row = tid >> 2;
            int k4  = (tid & 3) << 2;
            float4 v = *(const float4*)&W[(size_t)(n0 + row) * 256 + k0 + k4];
            sW[row][k4 + 0] = v.x; sW[row][k4 + 1] = v.y;
            sW[row][k4 + 2] = v.z; sW[row][k4 + 3] = v.w;
        }
        __syncthreads();
#pragma unroll
        for (int k = 0; k < 16; k++) {
            float a[8], w[4];
#pragma unroll
            for (int i = 0; i < 8; i++) a[i] = sA[(tr << 3) + i][k];
#pragma unroll
            for (int j = 0; j < 4; j++) w[j] = sW[(tc << 2) + j][k];
#pragma unroll
            for (int i = 0; i < 8; i++)
#pragma unroll
                for (int j = 0; j < 4; j++) acc[i][j] += a[i] * w[j];
        }
        __syncthreads();
    }
    int n = n0 + (tc << 2);
    float b0 = bias[n + 0], b1 = bias[n + 1], b2 = bias[n + 2], b3 = bias[n + 3];
#pragma unroll
    for (int i = 0; i < 8; i++) {
        float4 o;
        o.x = acc[i][0] + b0; o.y = acc[i][1] + b1;
        o.z = acc[i][2] + b2; o.w = acc[i][3] + b3;
        *(float4*)&C[(size_t)(m0 + (tr << 3) + i) * 256 + n] = o;
    }
}

// =====================================================================================
// Fused per-tile kernel: attention (4 heads) + out_proj + LayerNorm + masked col-sum.
// One tile = up to 32 struct tokens of ONE batch. 256 threads / block.
// =====================================================================================
__global__ __launch_bounds__(256) void attn_tile_kernel(
    const float* __restrict__ lnw, const float* __restrict__ lnb,
    const float* __restrict__ outW, const float* __restrict__ outB)
{
    extern __shared__ float sm[];
    int tile = blockIdx.x;
    if (tile >= g_ntiles) return;
    int b    = g_tileB[tile];
    int s0   = g_tileStart[tile];
    int rows = g_tileRows[tile];

    int tid  = threadIdx.x;
    int warp = tid >> 5;
    int lane = tid & 31;

    // ---- load Q tile [32][256] (pad invalid rows with 0) + zero col-sums ----
#pragma unroll
    for (int t = 0; t < 8; t++) {
        int f4  = tid + (t << 8);
        int row = f4 >> 6;
        int c4  = (f4 & 63) << 2;
        float4 v = make_float4(0.f, 0.f, 0.f, 0.f);
        if (row < rows) v = *(const float4*)&g_Q[(size_t)(s0 + row) * 256 + c4];
        *(float4*)&sm[SQ_OFF + row * 260 + c4] = v;
    }
    sm[COL_OFF + tid] = 0.f;
    __syncthreads();

    // ---- attention per head ----
    for (int h = 0; h < HEADS; h++) {
        // load K_h : [256 keys][64 dims], row stride 65 (conflict-free inner loop)
#pragma unroll
        for (int t = 0; t < 16; t++) {
            int f4 = tid + (t << 8);
            int j  = f4 >> 4;
            int d4 = (f4 & 15) << 2;
            float4 kv = *(const float4*)&g_K[(size_t)((b << 8) + j) * 256 + (h << 6) + d4];
            float* dst = &sm[KV_OFF + j * 65 + d4];
            dst[0] = kv.x; dst[1] = kv.y; dst[2] = kv.z; dst[3] = kv.w;
        }
        __syncthreads();

        // scores: warp handles rows warp*4..+3, lane handles keys lane+32*jj
        float acc[4][8];
#pragma unroll
        for (int ii = 0; ii < 4; ii++)
#pragma unroll
            for (int jj = 0; jj < 8; jj++) acc[ii][jj] = 0.f;

        int qrow = (warp << 2) * 260 + (h << 6);
#pragma unroll 4
        for (int k = 0; k < 64; k++) {
            float q0 = sm[SQ_OFF + qrow + 0 * 260 + k];
            float q1 = sm[SQ_OFF + qrow + 1 * 260 + k];
            float q2 = sm[SQ_OFF + qrow + 2 * 260 + k];
            float q3 = sm[SQ_OFF + qrow + 3 * 260 + k];
#pragma unroll
            for (int jj = 0; jj < 8; jj++) {
                float w = sm[KV_OFF + (lane + (jj << 5)) * 65 + k];
                acc[0][jj] += q0 * w; acc[1][jj] += q1 * w;
                acc[2][jj] += q2 * w; acc[3][jj] += q3 * w;
            }
        }

        // softmax per row (across the 32 lanes of this warp)
#pragma unroll
        for (int ii = 0; ii < 4; ii++) {
            float m = -1e30f;
#pragma unroll
            for (int jj = 0; jj < 8; jj++) {
                float s = acc[ii][jj] * 0.125f;   // 1/sqrt(64)
                acc[ii][jj] = s;
                m = fmaxf(m, s);
            }
#pragma unroll
            for (int off = 16; off > 0; off >>= 1)
                m = fmaxf(m, __shfl_xor_sync(0xffffffffu, m, off));
            float sum = 0.f;
#pragma unroll
            for (int jj = 0; jj < 8; jj++) {
                float p = __expf(acc[ii][jj] - m);
                acc[ii][jj] = p;
                sum += p;
            }
#pragma unroll
            for (int off = 16; off > 0; off >>= 1)
                sum += __shfl_xor_sync(0xffffffffu, sum, off);
            float inv = 1.f / sum;
            int srow = ((warp << 2) + ii) * 260;
#pragma unroll
            for (int jj = 0; jj < 8; jj++)
                sm[SS_OFF + srow + lane + (jj << 5)] = acc[ii][jj] * inv;
        }
        __syncthreads();

        // load V_h : [256 keys][64 dims], row stride 68 (16B-aligned float4 stores)
#pragma unroll
        for (int t = 0; t < 16; t++) {
            int f4 = tid + (t << 8);
            int j  = f4 >> 4;
            int d4 = (f4 & 15) << 2;
            float4 vv = *(const float4*)&g_V[(size_t)((b << 8) + j) * 256 + (h << 6) + d4];
            *(float4*)&sm[KV_OFF + j * 68 + d4] = vv;
        }
        __syncthreads();

        // ctx: thread -> (row i = tid>>3, dim block = (tid&7)*8)
        {
            int ci   = tid >> 3;
            int dblk = (tid & 7) << 3;
            float c[8];
#pragma unroll
            for (int u = 0; u < 8; u++) c[u] = 0.f;
            int prow = SS_OFF + ci * 260;
#pragma unroll 4
            for (int j = 0; j < 256; j++) {
                float p = sm[prow + j];
                float4 v0 = *(const float4*)&sm[KV_OFF + j * 68 + dblk];
                float4 v1 = *(const float4*)&sm[KV_OFF + j * 68 + dblk + 4];
                c[0] += p * v0.x; c[1] += p * v0.y; c[2] += p * v0.z; c[3] += p * v0.w;
                c[4] += p * v1.x; c[5] += p * v1.y; c[6] += p * v1.z; c[7] += p * v1.w;
            }
            float4 o0 = make_float4(c[0], c[1], c[2], c[3]);
            float4 o1 = make_float4(c[4], c[5], c[6], c[7]);
            *(float4*)&sm[SC_OFF + ci * 260 + (h << 6) + dblk] = o0;
            *(float4*)&sm[SC_OFF + ci * 260 + (h << 6) + dblk + 4] = o1;
        }
        __syncthreads();
    }

    // ---- out_proj: fused[32][256] = ctx @ Wo^T + bo, staged by 64-col chunks ----
    for (int nc = 0; nc < 4; nc++) {
        int n0 = nc << 6;
#pragma unroll
        for (int t = 0; t < 16; t++) {
            int f4   = tid + (t << 8);
            int nloc = f4 >> 6;
            int k4   = (f4 & 63) << 2;
            float4 w = *(const float4*)&outW[(size_t)(n0 + nloc) * 256 + k4];
            float* dst = &sm[KV_OFF + nloc * 257 + k4];
            dst[0] = w.x; dst[1] = w.y; dst[2] = w.z; dst[3] = w.w;
        }
        __syncthreads();

        float f[4][2];
#pragma unroll
        for (int ii = 0; ii < 4; ii++) { f[ii][0] = 0.f; f[ii][1] = 0.f; }
        int crow = SC_OFF + (warp << 2) * 260;
        int w0r  = KV_OFF + lane * 257;
        int w1r  = KV_OFF + (lane + 32) * 257;
#pragma unroll 4
        for (int k = 0; k < 256; k++) {
            float a0 = sm[crow + 0 * 260 + k];
            float a1 = sm[crow + 1 * 260 + k];
            float a2 = sm[crow + 2 * 260 + k];
            float a3 = sm[crow + 3 * 260 + k];
            float w0 = sm[w0r + k];
            float w1 = sm[w1r + k];
            f[0][0] += a0 * w0; f[0][1] += a0 * w1;
            f[1][0] += a1 * w0; f[1][1] += a1 * w1;
            f[2][0] += a2 * w0; f[2][1] += a2 * w1;
            f[3][0] += a3 * w0; f[3][1] += a3 * w1;
        }
        float bo0 = __ldg(&outB[n0 + lane]);
        float bo1 = __ldg(&outB[n0 + lane + 32]);
#pragma unroll
        for (int ii = 0; ii < 4; ii++) {
            int srow = ((warp << 2) + ii) * 260;
            sm[SS_OFF + srow + n0 + lane]      = f[ii][0] + bo0;
            sm[SS_OFF + srow + n0 + lane + 32] = f[ii][1] + bo1;
        }
        __syncthreads();
    }

    // ---- LayerNorm + masked column sum ----
#pragma unroll
    for (int ii = 0; ii < 4; ii++) {
        int row = (warp << 2) + ii;
        float x[8];
        float s = 0.f, ss = 0.f;
        int srow = SS_OFF + row * 260;
#pragma unroll
        for (int t = 0; t < 8; t++) {
            float v = sm[srow + lane + (t << 5)];
            x[t] = v;
            s += v; ss += v * v;
        }
#pragma unroll
        for (int off = 16; off > 0; off >>= 1) {
            s  += __shfl_xor_sync(0xffffffffu, s, off);
            ss += __shfl_xor_sync(0xffffffffu, ss, off);
        }
        float mu  = s * (1.f / 256.f);
        float var = ss * (1.f / 256.f) - mu * mu;
        float inv = rsqrtf(var + 1e-5f);
        if (row < rows) {
#pragma unroll
            for (int t = 0; t < 8; t++) {
                int n = lane + (t << 5);
                float y = (x[t] - mu) * inv * __ldg(&lnw[n]) + __ldg(&lnb[n]);
                atomicAdd(&sm[COL_OFF + n], y);
            }
        }
    }
    __syncthreads();
    atomicAdd(&g_accum[(b << 8) + tid], sm[COL_OFF + tid]);
}

// =====================================================================================
// Finalize: out[b] = (accum[b] / max(cnt,1)) @ fc^T + fc_b  (0 for empty batches).
// =====================================================================================
__global__ __launch_bounds__(256) void finalize_kernel(
    const float* __restrict__ fcw, const float* __restrict__ fcb,
    float* __restrict__ out)
{
    int b = blockIdx.x;
    int tid = threadIdx.x;
    __shared__ float s[256];
    s[tid] = g_accum[(b << 8) + tid];
    __syncthreads();
    int cnt = g_offsets[b + 1] - g_offsets[b];
    if (cnt == 0) { out[(b << 8) + tid] = 0.f; return; }
    float acc = 0.f;
    const float* wrow = fcw + (size_t)tid * 256;
#pragma unroll 8
    for (int k = 0; k < 256; k++) acc += s[k] * __ldg(&wrow[k]);
    out[(b << 8) + tid] = acc / (float)cnt + __ldg(&fcb[tid]);
}

// =====================================================================================
// Launch
// =====================================================================================
extern "C" void kernel_launch(void* const* d_in, const int* in_sizes, int n_in,
                              void* d_out, int out_size)
{
    const float* structf = (const float*)d_in[0];
    const float* textf   = (const float*)d_in[1];
    const int*   sb      = (const int*)d_in[2];
    const float* inW     = (const float*)d_in[3];
    const float* inB     = (const float*)d_in[4];
    const float* outW    = (const float*)d_in[5];
    const float* outB    = (const float*)d_in[6];
    const float* lnw     = (const float*)d_in[7];
    const float* lnb     = (const float*)d_in[8];
    const float* fcw     = (const float*)d_in[9];
    const float* fcb     = (const float*)d_in[10];
    float* out = (float*)d_out;

    float *pQ, *pK, *pV;
    cudaGetSymbolAddress((void**)&pQ, g_Q);
    cudaGetSymbolAddress((void**)&pK, g_K);
    cudaGetSymbolAddress((void**)&pV, g_V);
    cudaFuncSetAttribute(attn_tile_kernel,
                         cudaFuncAttributeMaxDynamicSharedMemorySize, SMEM_BYTES);

    setup_kernel<<<1, 256>>>(sb);

    // K = text @ Wk^T + bk ; V = text @ Wv^T + bv  (M = 16384)
    gemm256<<<dim3((B_BATCH * L_TEXT) / 128, 4), 256>>>(textf, inW + DIM * DIM,     inB + DIM,     pK);
    gemm256<<<dim3((B_BATCH * L_TEXT) / 128, 4), 256>>>(textf, inW + 2 * DIM * DIM, inB + 2 * DIM, pV);
    // Q = struct @ Wq^T + bq  (M = 65536)
    gemm256<<<dim3(N_STRUCT / 128, 4), 256>>>(structf, inW, inB, pQ);

    attn_tile_kernel<<<MAXT, 256, SMEM_BYTES>>>(lnw, lnb, outW, outB);
    finalize_kernel<<<B_BATCH, 256>>>(fcw, fcb, out);
}

// round 2
// speedup vs baseline: 4.4205x; 4.4205x over previous
#include <cuda_runtime.h>
#include <cstdint>

#define N_STRUCT 65536
#define B_BATCH  64
#define L_TEXT   256
#define DIM      256
#define TM2      64
#define MAXT     (B_BATCH + N_STRUCT / TM2)   // 1088

// ---------------- scratch ----------------
__device__ float g_Q[N_STRUCT * DIM];
__device__ float g_K[B_BATCH * L_TEXT * DIM];
__device__ float g_V[B_BATCH * L_TEXT * DIM];
__device__ float g_Ctx[N_STRUCT * DIM];
__device__ float g_accum[B_BATCH * DIM];
__device__ int   g_offsets[B_BATCH + 1];
__device__ int   g_tileB[MAXT];
__device__ int   g_tileStart[MAXT];
__device__ int   g_tileRows[MAXT];
__device__ int   g_ntiles;
__device__ int   g_is64;

// ---------------- helpers ----------------
__device__ __forceinline__ float tf32r(float x) {
    uint32_t u;
    asm("cvt.rna.tf32.f32 %0, %1;" : "=r"(u) : "f"(x));
    return __uint_as_float(u);
}
__device__ __forceinline__ void mma8(float* c, const uint32_t* a, const uint32_t* b) {
    asm volatile(
        "mma.sync.aligned.m16n8k8.row.col.f32.tf32.tf32.f32 "
        "{%0,%1,%2,%3},{%4,%5,%6,%7},{%8,%9},{%0,%1,%2,%3};"
        : "+f"(c[0]), "+f"(c[1]), "+f"(c[2]), "+f"(c[3])
        : "r"(a[0]), "r"(a[1]), "r"(a[2]), "r"(a[3]), "r"(b[0]), "r"(b[1]));
}
__device__ __forceinline__ uint32_t fasu(float x) { return __float_as_uint(x); }

// =====================================================================================
// Setup: dtype detect, batch offsets, tile schedule (TM2 rows/tile), zero accum.
// =====================================================================================
__global__ void setup_kernel(const int* __restrict__ sb)
{
    __shared__ int sIs64;
    __shared__ int sOff[B_BATCH + 1];
    __shared__ int sScan[B_BATCH + 1];
    int tid = threadIdx.x;

    if (tid == 0) {
        sIs64 = (sb[N_STRUCT - 1] == 0) ? 1 : 0;
        g_is64 = sIs64;
    }
    for (int i = tid; i < B_BATCH * DIM; i += blockDim.x) g_accum[i] = 0.f;
    __syncthreads();
    int is64 = sIs64;

    if (tid <= B_BATCH) {
        int lo = 0, hi = N_STRUCT;
        while (lo < hi) {
            int mid = (lo + hi) >> 1;
            int v = is64 ? sb[2 * mid] : sb[mid];
            if (v < tid) lo = mid + 1; else hi = mid;
        }
        sOff[tid] = lo;
        g_offsets[tid] = lo;
    }
    __syncthreads();
    if (tid < B_BATCH) {
        int cnt = sOff[tid + 1] - sOff[tid];
        sScan[tid] = (cnt + TM2 - 1) / TM2;
    }
    __syncthreads();
    if (tid == 0) {
        int run = 0;
        for (int i = 0; i < B_BATCH; i++) { int t = sScan[i]; sScan[i] = run; run += t; }
        g_ntiles = run;
    }
    __syncthreads();
    if (tid < B_BATCH) {
        int base = sScan[tid];
        int off  = sOff[tid];
        int cnt  = sOff[tid + 1] - off;
        for (int t = 0; t * TM2 < cnt; t++) {
            g_tileB[base + t]     = tid;
            g_tileStart[base + t] = off + t * TM2;
            g_tileRows[base + t]  = min(TM2, cnt - t * TM2);
        }
    }
}

// =====================================================================================
// K1: tf32 tensor GEMM  C[M x 256] = A[M x 256] @ W^T + bias.
// Tile 128(M) x 128(N) x 32(K). 256 threads, 8 warps as 4(M) x 2(N); warp tile 32x64.
// =====================================================================================
__global__ __launch_bounds__(256) void gemm_tc(
    const float* __restrict__ A, const float* __restrict__ W,
    const float* __restrict__ bias, float* __restrict__ C)
{
    __shared__ float sA[128 * 36];
    __shared__ float sW[128 * 36];
    int tid = threadIdx.x;
    int w = tid >> 5, lane = tid & 31;
    int g = lane >> 2, t = lane & 3;
    int wm = w >> 1, wn = w & 1;
    int m0 = blockIdx.x << 7, n0 = blockIdx.y << 7;

    float acc[2][8][4];
#pragma unroll
    for (int mt = 0; mt < 2; mt++)
#pragma unroll
        for (int nt = 0; nt < 8; nt++)
#pragma unroll
            for (int r = 0; r < 4; r++) acc[mt][nt][r] = 0.f;

    for (int k0 = 0; k0 < 256; k0 += 32) {
#pragma unroll
        for (int q = 0; q < 4; q++) {
            int f4 = tid + (q << 8);
            int row = f4 >> 3;
            int c4 = (f4 & 7) << 2;
            float4 va = *(const float4*)&A[(size_t)(m0 + row) * 256 + k0 + c4];
            float4 vw = *(const float4*)&W[(size_t)(n0 + row) * 256 + k0 + c4];
            float* da = &sA[row * 36 + c4];
            float* dw = &sW[row * 36 + c4];
            da[0] = tf32r(va.x); da[1] = tf32r(va.y); da[2] = tf32r(va.z); da[3] = tf32r(va.w);
            dw[0] = tf32r(vw.x); dw[1] = tf32r(vw.y); dw[2] = tf32r(vw.z); dw[3] = tf32r(vw.w);
        }
        __syncthreads();
#pragma unroll
        for (int ks = 0; ks < 4; ks++) {
            uint32_t af[2][4];
#pragma unroll
            for (int mt = 0; mt < 2; mt++) {
                int base = (wm * 32 + mt * 16 + g) * 36 + ks * 8 + t;
                af[mt][0] = fasu(sA[base]);
                af[mt][1] = fasu(sA[base + 8 * 36]);
                af[mt][2] = fasu(sA[base + 4]);
                af[mt][3] = fasu(sA[base + 8 * 36 + 4]);
            }
#pragma unroll
            for (int nt = 0; nt < 8; nt++) {
                int nb = (wn * 64 + nt * 8 + g) * 36 + ks * 8 + t;
                uint32_t bf[2];
                bf[0] = fasu(sW[nb]);
                bf[1] = fasu(sW[nb + 4]);
                mma8(acc[0][nt], af[0], bf);
                mma8(acc[1][nt], af[1], bf);
            }
        }
        __syncthreads();
    }
#pragma unroll
    for (int mt = 0; mt < 2; mt++) {
        int row = m0 + wm * 32 + mt * 16 + g;
#pragma unroll
        for (int nt = 0; nt < 8; nt++) {
            int col = n0 + wn * 64 + nt * 8 + t * 2;
            float b0 = __ldg(&bias[col]), b1 = __ldg(&bias[col + 1]);
            float2 o0 = make_float2(acc[mt][nt][0] + b0, acc[mt][nt][1] + b1);
            float2 o1 = make_float2(acc[mt][nt][2] + b0, acc[mt][nt][3] + b1);
            *(float2*)&C[(size_t)row * 256 + col] = o0;
            *(float2*)&C[(size_t)(row + 8) * 256 + col] = o1;
        }
    }
}

// =====================================================================================
// K2a: attention per tile of 64 query rows (one batch), 4 heads, tensor cores.
// =====================================================================================
#define QA_OFF 0
#define KV_OFF 4352
#define PP_OFF 21760
#define RM_OFF 38400
#define RS_OFF 38656
#define K2A_FLOATS 38912
#define K2A_BYTES (K2A_FLOATS * 4)

__global__ __launch_bounds__(256) void attn_tc()
{
    extern __shared__ float sm[];
    int tile = blockIdx.x;
    if (tile >= g_ntiles) return;
    int b    = g_tileB[tile];
    int s0   = g_tileStart[tile];
    int rows = g_tileRows[tile];

    int tid = threadIdx.x;
    int w = tid >> 5, lane = tid & 31;
    int g = lane >> 2, t = lane & 3;
    int wm = w >> 2, wn = w & 3;     // scores: 2(M) x 4(N); ctx reuses same split

    for (int h = 0; h < 4; h++) {
        // ---- load Q_h [64x64] (tf32), zero pad rows ----
#pragma unroll
        for (int q = 0; q < 4; q++) {
            int f4 = tid + (q << 8);
            int row = f4 >> 4;
            int c4 = (f4 & 15) << 2;
            float4 v = make_float4(0.f, 0.f, 0.f, 0.f);
            if (row < rows)
                v = *(const float4*)&g_Q[(size_t)(s0 + row) * 256 + (h << 6) + c4];
            float* d = &sm[QA_OFF + row * 68 + c4];
            d[0] = tf32r(v.x); d[1] = tf32r(v.y); d[2] = tf32r(v.z); d[3] = tf32r(v.w);
        }
        // ---- load K_h [256x64] (tf32) ----
#pragma unroll
        for (int q = 0; q < 16; q++) {
            int f4 = tid + (q << 8);
            int key = f4 >> 4;
            int c4 = (f4 & 15) << 2;
            float4 v = *(const float4*)&g_K[(size_t)((b << 8) + key) * 256 + (h << 6) + c4];
            float* d = &sm[KV_OFF + key * 68 + c4];
            d[0] = tf32r(v.x); d[1] = tf32r(v.y); d[2] = tf32r(v.z); d[3] = tf32r(v.w);
        }
        __syncthreads();

        // ---- scores: S[64x256] = Q_h @ K_h^T, warp tile 32(M) x 64(N) ----
        float sc[2][8][4];
#pragma unroll
        for (int mt = 0; mt < 2; mt++)
#pragma unroll
            for (int nt = 0; nt < 8; nt++)
#pragma unroll
                for (int r = 0; r < 4; r++) sc[mt][nt][r] = 0.f;

#pragma unroll
        for (int ks = 0; ks < 8; ks++) {
            uint32_t af[2][4];
#pragma unroll
            for (int mt = 0; mt < 2; mt++) {
                int base = QA_OFF + (wm * 32 + mt * 16 + g) * 68 + ks * 8 + t;
                af[mt][0] = fasu(sm[base]);
                af[mt][1] = fasu(sm[base + 8 * 68]);
                af[mt][2] = fasu(sm[base + 4]);
                af[mt][3] = fasu(sm[base + 8 * 68 + 4]);
            }
#pragma unroll
            for (int nt = 0; nt < 8; nt++) {
                int nb = KV_OFF + (wn * 64 + nt * 8 + g) * 68 + ks * 8 + t;
                uint32_t bf[2];
                bf[0] = fasu(sm[nb]);
                bf[1] = fasu(sm[nb + 4]);
                mma8(sc[0][nt], af[0], bf);
                mma8(sc[1][nt], af[1], bf);
            }
        }

        // ---- softmax across rows (each row spans 4 warps) ----
        float mx[4];
#pragma unroll
        for (int rid = 0; rid < 4; rid++) {
            int mt = rid >> 1, h2 = rid & 1;
            float m = -1e30f;
#pragma unroll
            for (int nt = 0; nt < 8; nt++)
#pragma unroll
                for (int j = 0; j < 2; j++) {
                    float v = sc[mt][nt][h2 * 2 + j] * 0.125f;
                    sc[mt][nt][h2 * 2 + j] = v;
                    m = fmaxf(m, v);
                }
            m = fmaxf(m, __shfl_xor_sync(0xffffffffu, m, 1));
            m = fmaxf(m, __shfl_xor_sync(0xffffffffu, m, 2));
            mx[rid] = m;
        }
        if (t == 0) {
#pragma unroll
            for (int rid = 0; rid < 4; rid++) {
                int r = wm * 32 + (rid >> 1) * 16 + g + (rid & 1) * 8;
                sm[RM_OFF + wn * 64 + r] = mx[rid];
            }
        }
        __syncthreads();
        float inv4[4];
        float mf[4];
#pragma unroll
        for (int rid = 0; rid < 4; rid++) {
            int r = wm * 32 + (rid >> 1) * 16 + g + (rid & 1) * 8;
            float m = sm[RM_OFF + r];
            m = fmaxf(m, sm[RM_OFF + 64 + r]);
            m = fmaxf(m, sm[RM_OFF + 128 + r]);
            m = fmaxf(m, sm[RM_OFF + 192 + r]);
            mf[rid] = m;
        }
        float sums[4];
#pragma unroll
        for (int rid = 0; rid < 4; rid++) {
            int mt = rid >> 1, h2 = rid & 1;
            float s = 0.f;
#pragma unroll
            for (int nt = 0; nt < 8; nt++)
#pragma unroll
                for (int j = 0; j < 2; j++) {
                    float p = __expf(sc[mt][nt][h2 * 2 + j] - mf[rid]);
                    sc[mt][nt][h2 * 2 + j] = p;
                    s += p;
                }
            s += __shfl_xor_sync(0xffffffffu, s, 1);
            s += __shfl_xor_sync(0xffffffffu, s, 2);
            sums[rid] = s;
        }
        if (t == 0) {
#pragma unroll
            for (int rid = 0; rid < 4; rid++) {
                int r = wm * 32 + (rid >> 1) * 16 + g + (rid & 1) * 8;
                sm[RS_OFF + wn * 64 + r] = sums[rid];
            }
        }
        __syncthreads();
#pragma unroll
        for (int rid = 0; rid < 4; rid++) {
            int r = wm * 32 + (rid >> 1) * 16 + g + (rid & 1) * 8;
            float tot = sm[RS_OFF + r] + sm[RS_OFF + 64 + r] +
                        sm[RS_OFF + 128 + r] + sm[RS_OFF + 192 + r];
            inv4[rid] = 1.f / tot;
        }
        // store P (tf32)
#pragma unroll
        for (int rid = 0; rid < 4; rid++) {
            int mt = rid >> 1, h2 = rid & 1;
            int r = wm * 32 + mt * 16 + g + h2 * 8;
#pragma unroll
            for (int nt = 0; nt < 8; nt++) {
                int col = wn * 64 + nt * 8 + t * 2;
                sm[PP_OFF + r * 260 + col]     = tf32r(sc[mt][nt][h2 * 2] * inv4[rid]);
                sm[PP_OFF + r * 260 + col + 1] = tf32r(sc[mt][nt][h2 * 2 + 1] * inv4[rid]);
            }
        }
        __syncthreads();

        // ---- load V_h [256x64] (tf32), overwrite K ----
#pragma unroll
        for (int q = 0; q < 16; q++) {
            int f4 = tid + (q << 8);
            int key = f4 >> 4;
            int c4 = (f4 & 15) << 2;
            float4 v = *(const float4*)&g_V[(size_t)((b << 8) + key) * 256 + (h << 6) + c4];
            float* d = &sm[KV_OFF + key * 68 + c4];
            d[0] = tf32r(v.x); d[1] = tf32r(v.y); d[2] = tf32r(v.z); d[3] = tf32r(v.w);
        }
        __syncthreads();

        // ---- ctx: C[64x64] = P @ V_h, warp tile 32(M) x 16(N) ----
        float cc[2][2][4];
#pragma unroll
        for (int mt = 0; mt < 2; mt++)
#pragma unroll
            for (int nt = 0; nt < 2; nt++)
#pragma unroll
                for (int r = 0; r < 4; r++) cc[mt][nt][r] = 0.f;

#pragma unroll 8
        for (int ks = 0; ks < 32; ks++) {
            uint32_t af[2][4];
#pragma unroll
            for (int mt = 0; mt < 2; mt++) {
                int base = PP_OFF + (wm * 32 + mt * 16 + g) * 260 + ks * 8 + t;
                af[mt][0] = fasu(sm[base]);
                af[mt][1] = fasu(sm[base + 8 * 260]);
                af[mt][2] = fasu(sm[base + 4]);
                af[mt][3] = fasu(sm[base + 8 * 260 + 4]);
            }
#pragma unroll
            for (int nt = 0; nt < 2; nt++) {
                int nb = KV_OFF + (ks * 8 + t) * 68 + wn * 16 + nt * 8 + g;
                uint32_t bf[2];
                bf[0] = fasu(sm[nb]);
                bf[1] = fasu(sm[nb + 4 * 68]);
                mma8(cc[0][nt], af[0], bf);
                mma8(cc[1][nt], af[1], bf);
            }
        }
        // write ctx head block
#pragma unroll
        for (int mt = 0; mt < 2; mt++)
#pragma unroll
            for (int h2 = 0; h2 < 2; h2++) {
                int r = wm * 32 + mt * 16 + g + h2 * 8;
                if (r < rows) {
#pragma unroll
                    for (int nt = 0; nt < 2; nt++) {
                        int col = (h << 6) + wn * 16 + nt * 8 + t * 2;
                        float2 o = make_float2(cc[mt][nt][h2 * 2], cc[mt][nt][h2 * 2 + 1]);
                        *(float2*)&g_Ctx[(size_t)(s0 + r) * 256 + col] = o;
                    }
                }
            }
        __syncthreads();
    }
}

// =====================================================================================
// K2b: fused = ctx @ Wo^T + bo; LayerNorm; per-batch column accumulation.
// Tile 64(M) x 256(N) x 32(K). 8 warps as 2(M) x 4(N); warp tile 32x64.
// =====================================================================================
#define OB_A   0
#define OB_W   2304
#define OB_OUT 0
#define OB_RM  16640
#define OB_RS  16896
#define OB_RB  17152
#define K2B_FLOATS 17216
#define K2B_BYTES (K2B_FLOATS * 4)

__global__ __launch_bounds__(256) void outln_tc(
    const float* __restrict__ Wo, const float* __restrict__ bo,
    const float* __restrict__ lnw, const float* __restrict__ lnb,
    const int* __restrict__ sb)
{
    extern __shared__ float sm[];
    int* rowB = (int*)&sm[OB_RB];
    int tid = threadIdx.x;
    int w = tid >> 5, lane = tid & 31;
    int g = lane >> 2, t = lane & 3;
    int wm = w >> 2, wn = w & 3;
    int m0 = blockIdx.x << 6;

    if (tid < 64) {
        int idx = m0 + tid;
        rowB[tid] = g_is64 ? sb[2 * idx] : sb[idx];
    }

    float acc[2][8][4];
#pragma unroll
    for (int mt = 0; mt < 2; mt++)
#pragma unroll
        for (int nt = 0; nt < 8; nt++)
#pragma unroll
            for (int r = 0; r < 4; r++) acc[mt][nt][r] = 0.f;

    for (int kc = 0; kc < 8; kc++) {
        int k0 = kc << 5;
#pragma unroll
        for (int q = 0; q < 2; q++) {
            int f4 = tid + (q << 8);
            int row = f4 >> 3;
            int c4 = (f4 & 7) << 2;
            float4 v = *(const float4*)&g_Ctx[(size_t)(m0 + row) * 256 + k0 + c4];
            float* d = &sm[OB_A + row * 36 + c4];
            d[0] = tf32r(v.x); d[1] = tf32r(v.y); d[2] = tf32r(v.z); d[3] = tf32r(v.w);
        }
#pragma unroll
        for (int q = 0; q < 8; q++) {
            int f4 = tid + (q << 8);
            int row = f4 >> 3;
            int c4 = (f4 & 7) << 2;
            float4 v = *(const float4*)&Wo[(size_t)row * 256 + k0 + c4];
            float* d = &sm[OB_W + row * 36 + c4];
            d[0] = tf32r(v.x); d[1] = tf32r(v.y); d[2] = tf32r(v.z); d[3] = tf32r(v.w);
        }
        __syncthreads();
#pragma unroll
        for (int ks = 0; ks < 4; ks++) {
            uint32_t af[2][4];
#pragma unroll
            for (int mt = 0; mt < 2; mt++) {
                int base = OB_A + (wm * 32 + mt * 16 + g) * 36 + ks * 8 + t;
                af[mt][0] = fasu(sm[base]);
                af[mt][1] = fasu(sm[base + 8 * 36]);
                af[mt][2] = fasu(sm[base + 4]);
                af[mt][3] = fasu(sm[base + 8 * 36 + 4]);
            }
#pragma unroll
            for (int nt = 0; nt < 8; nt++) {
                int nb = OB_W + (wn * 64 + nt * 8 + g) * 36 + ks * 8 + t;
                uint32_t bf[2];
                bf[0] = fasu(sm[nb]);
                bf[1] = fasu(sm[nb + 4]);
                mma8(acc[0][nt], af[0], bf);
                mma8(acc[1][nt], af[1], bf);
            }
        }
        __syncthreads();
    }

    // bias
#pragma unroll
    for (int nt = 0; nt < 8; nt++) {
        int col = wn * 64 + nt * 8 + t * 2;
        float b0 = __ldg(&bo[col]), b1 = __ldg(&bo[col + 1]);
#pragma unroll
        for (int mt = 0; mt < 2; mt++) {
            acc[mt][nt][0] += b0; acc[mt][nt][1] += b1;
            acc[mt][nt][2] += b0; acc[mt][nt][3] += b1;
        }
    }

    // LN stats (row spans 4 warps)
    float s4[4], q4[4];
#pragma unroll
    for (int rid = 0; rid < 4; rid++) {
        int mt = rid >> 1, h2 = rid & 1;
        float s = 0.f, qq = 0.f;
#pragma unroll
        for (int nt = 0; nt < 8; nt++)
#pragma unroll
            for (int j = 0; j < 2; j++) {
                float v = acc[mt][nt][h2 * 2 + j];
                s += v; qq += v * v;
            }
        s  += __shfl_xor_sync(0xffffffffu, s, 1);
        s  += __shfl_xor_sync(0xffffffffu, s, 2);
        qq += __shfl_xor_sync(0xffffffffu, qq, 1);
        qq += __shfl_xor_sync(0xffffffffu, qq, 2);
        s4[rid] = s; q4[rid] = qq;
    }
    if (t == 0) {
#pragma unroll
        for (int rid = 0; rid < 4; rid++) {
            int r = wm * 32 + (rid >> 1) * 16 + g + (rid & 1) * 8;
            sm[OB_RM + wn * 64 + r] = s4[rid];
            sm[OB_RS + wn * 64 + r] = q4[rid];
        }
    }
    __syncthreads();
    float mu[4], inv[4];
#pragma unroll
    for (int rid = 0; rid < 4; rid++) {
        int r = wm * 32 + (rid >> 1) * 16 + g + (rid & 1) * 8;
        float S  = sm[OB_RM + r] + sm[OB_RM + 64 + r] + sm[OB_RM + 128 + r] + sm[OB_RM + 192 + r];
        float SQ = sm[OB_RS + r] + sm[OB_RS + 64 + r] + sm[OB_RS + 128 + r] + sm[OB_RS + 192 + r];
        float m = S * (1.f / 256.f);
        float var = SQ * (1.f / 256.f) - m * m;
        mu[rid] = m;
        inv[rid] = rsqrtf(var + 1e-5f);
    }
    // normalize and store to sOut (overlays GEMM smem; GEMM reads done)
#pragma unroll
    for (int rid = 0; rid < 4; rid++) {
        int mt = rid >> 1, h2 = rid & 1;
        int r = wm * 32 + mt * 16 + g + h2 * 8;
#pragma unroll
        for (int nt = 0; nt < 8; nt++) {
            int col = wn * 64 + nt * 8 + t * 2;
            float y0 = (acc[mt][nt][h2 * 2]     - mu[rid]) * inv[rid] * __ldg(&lnw[col])     + __ldg(&lnb[col]);
            float y1 = (acc[mt][nt][h2 * 2 + 1] - mu[rid]) * inv[rid] * __ldg(&lnw[col + 1]) + __ldg(&lnb[col + 1]);
            sm[OB_OUT + r * 260 + col]     = y0;
            sm[OB_OUT + r * 260 + col + 1] = y1;
        }
    }
    __syncthreads();

    // per-batch run-length accumulation; thread = column
    {
        int col = tid;
        float run = 0.f;
        int cur = rowB[0];
        for (int r = 0; r < 64; r++) {
            int bb = rowB[r];
            if (bb != cur) {
                atomicAdd(&g_accum[(cur << 8) + col], run);
                run = 0.f;
                cur = bb;
            }
            run += sm[OB_OUT + r * 260 + col];
        }
        atomicAdd(&g_accum[(cur << 8) + col], run);
    }
}

// =====================================================================================
// Finalize: out[b] = (accum[b]/cnt) @ fc^T + fc_b  (0 for empty batches).
// =====================================================================================
__global__ __launch_bounds__(256) void finalize_kernel(
    const float* __restrict__ fcw, const float* __restrict__ fcb,
    float* __restrict__ out)
{
    int b = blockIdx.x;
    int tid = threadIdx.x;
    __shared__ float s[256];
    s[tid] = g_accum[(b << 8) + tid];
    __syncthreads();
    int cnt = g_offsets[b + 1] - g_offsets[b];
    if (cnt == 0) { out[(b << 8) + tid] = 0.f; return; }
    float acc = 0.f;
    const float* wrow = fcw + (size_t)tid * 256;
#pragma unroll 8
    for (int k = 0; k < 256; k++) acc += s[k] * __ldg(&wrow[k]);
    out[(b << 8) + tid] = acc / (float)cnt + __ldg(&fcb[tid]);
}

// =====================================================================================
// Launch
// =====================================================================================
extern "C" void kernel_launch(void* const* d_in, const int* in_sizes, int n_in,
                              void* d_out, int out_size)
{
    const float* structf = (const float*)d_in[0];
    const float* textf   = (const float*)d_in[1];
    const int*   sb      = (const int*)d_in[2];
    const float* inW     = (const float*)d_in[3];
    const float* inB     = (const float*)d_in[4];
    const float* outW    = (const float*)d_in[5];
    const float* outB    = (const float*)d_in[6];
    const float* lnw     = (const float*)d_in[7];
    const float* lnb     = (const float*)d_in[8];
    const float* fcw     = (const float*)d_in[9];
    const float* fcb     = (const float*)d_in[10];
    float* out = (float*)d_out;

    float *pQ, *pK, *pV;
    cudaGetSymbolAddress((void**)&pQ, g_Q);
    cudaGetSymbolAddress((void**)&pK, g_K);
    cudaGetSymbolAddress((void**)&pV, g_V);

    cudaFuncSetAttribute(attn_tc, cudaFuncAttributeMaxDynamicSharedMemorySize, K2A_BYTES);
    cudaFuncSetAttribute(outln_tc, cudaFuncAttributeMaxDynamicSharedMemorySize, K2B_BYTES);

    setup_kernel<<<1, 256>>>(sb);

    gemm_tc<<<dim3((B_BATCH * L_TEXT) / 128, 2), 256>>>(textf, inW + DIM * DIM,     inB + DIM,     pK);
    gemm_tc<<<dim3((B_BATCH * L_TEXT) / 128, 2), 256>>>(textf, inW + 2 * DIM * DIM, inB + 2 * DIM, pV);
    gemm_tc<<<dim3(N_STRUCT / 128, 2), 256>>>(structf, inW, inB, pQ);

    attn_tc<<<MAXT, 256, K2A_BYTES>>>();
    outln_tc<<<N_STRUCT / 64, 256, K2B_BYTES>>>(outW, outB, lnw, lnb, sb);
    finalize_kernel<<<B_BATCH, 256>>>(fcw, fcb, out);
}